// round 1
// baseline (speedup 1.0000x reference)
#include <cuda_runtime.h>

// Per-quaternion L2 normalize: x (65536, 1024) fp32, viewed as (B, 256, 4).
// out[q] = x[q] / ||x[q]||, with ||x||==0 -> divide by 1.
// Pure HBM streaming: 512 MiB traffic, ~64 us floor at 8 TB/s.

static __device__ __forceinline__ float4 norm_quat(float4 v) {
    float s = v.x * v.x + v.y * v.y + v.z * v.z + v.w * v.w;
    // reference: norm==0 -> use 1.0 (i.e., pass through). sumsq==0 <=> norm==0.
    float inv = (s == 0.0f) ? 1.0f : rsqrtf(s);
    v.x *= inv; v.y *= inv; v.z *= inv; v.w *= inv;
    return v;
}

__global__ void __launch_bounds__(256)
quat_normalize_kernel(const float4* __restrict__ in,
                      float4* __restrict__ out,
                      int n_quat) {
    // 2 quaternions per thread, strided by blockDim within the block's tile
    // so both loads stay coalesced across the warp.
    int base = blockIdx.x * (blockDim.x * 2) + threadIdx.x;

    int i0 = base;
    int i1 = base + blockDim.x;

    if (i1 < n_quat) {
        float4 a = in[i0];
        float4 b = in[i1];
        out[i0] = norm_quat(a);
        out[i1] = norm_quat(b);
    } else if (i0 < n_quat) {
        out[i0] = norm_quat(in[i0]);
    }
}

extern "C" void kernel_launch(void* const* d_in, const int* in_sizes, int n_in,
                              void* d_out, int out_size) {
    const float4* x = (const float4*)d_in[0];
    float4* y = (float4*)d_out;
    int n_quat = in_sizes[0] / 4;   // 65536 * 1024 / 4 = 16,777,216

    const int threads = 256;
    const int per_block = threads * 2;
    int blocks = (n_quat + per_block - 1) / per_block;  // 32768
    quat_normalize_kernel<<<blocks, threads>>>(x, y, n_quat);
}

// round 2
// speedup vs baseline: 1.0086x; 1.0086x over previous
#include <cuda_runtime.h>

// Per-quaternion L2 normalize: x (65536, 1024) fp32 = (B, 256, 4) quats.
// Pure HBM stream: 512 MiB total. R1: 82.7us @ 5955 GB/s (DRAM 75.2%).
// R2: 4x front-batched float4/thread (MLP_p1=4) + .cs streaming hints,
//     exact grid (no predicates).

static __device__ __forceinline__ float4 norm_quat(float4 v) {
    float s = v.x * v.x + v.y * v.y + v.z * v.z + v.w * v.w;
    float inv = (s == 0.0f) ? 1.0f : rsqrtf(s);
    v.x *= inv; v.y *= inv; v.z *= inv; v.w *= inv;
    return v;
}

__global__ void __launch_bounds__(256)
quat_normalize_kernel(const float4* __restrict__ in,
                      float4* __restrict__ out) {
    const int T = 256;
    int base = blockIdx.x * (T * 4) + threadIdx.x;

    // Front-batch 4 independent 16B loads (coalesced across the warp at
    // each of the 4 strided offsets) -> 4 lines in flight per thread.
    float4 a = __ldcs(&in[base]);
    float4 b = __ldcs(&in[base + T]);
    float4 c = __ldcs(&in[base + 2 * T]);
    float4 d = __ldcs(&in[base + 3 * T]);

    a = norm_quat(a);
    b = norm_quat(b);
    c = norm_quat(c);
    d = norm_quat(d);

    __stcs(&out[base],         a);
    __stcs(&out[base + T],     b);
    __stcs(&out[base + 2 * T], c);
    __stcs(&out[base + 3 * T], d);
}

// Fallback with bounds checks in case sizes ever change (not used for the
// exact 2^24-quaternion shape).
__global__ void __launch_bounds__(256)
quat_normalize_tail_kernel(const float4* __restrict__ in,
                           float4* __restrict__ out,
                           int n_quat) {
    int i = blockIdx.x * blockDim.x + threadIdx.x;
    if (i < n_quat) out[i] = norm_quat(__ldcs(&in[i]));
}

extern "C" void kernel_launch(void* const* d_in, const int* in_sizes, int n_in,
                              void* d_out, int out_size) {
    const float4* x = (const float4*)d_in[0];
    float4* y = (float4*)d_out;
    int n_quat = in_sizes[0] / 4;   // 16,777,216

    const int threads = 256;
    const int per_block = threads * 4;  // 1024 quats/block

    if (n_quat % per_block == 0) {
        quat_normalize_kernel<<<n_quat / per_block, threads>>>(x, y);
    } else {
        int main_blocks = n_quat / per_block;
        if (main_blocks > 0)
            quat_normalize_kernel<<<main_blocks, threads>>>(x, y);
        int done = main_blocks * per_block;
        int rem = n_quat - done;
        if (rem > 0)
            quat_normalize_tail_kernel<<<(rem + threads - 1) / threads, threads>>>(
                x + done, y + done, rem);
    }
}